// round 1
// baseline (speedup 1.0000x reference)
#include <cuda_runtime.h>
#include <cstdint>

#define K3          27
#define PAIRS_PER_K 131072
#define N_VOX       262144
#define C_IN        32
#define C_OUT       32
#define M_TOTAL     (K3 * PAIRS_PER_K)
#define TPB         256

// ---------------------------------------------------------------------------
// Kernel 1: initialize output with bias (d_out is poisoned by harness).
// out[v][c] = bias[c]; vectorized as float4: N_VOX*8 float4 writes.
// ---------------------------------------------------------------------------
__global__ void init_bias_kernel(float4* __restrict__ out,
                                 const float4* __restrict__ bias4) {
    int t = blockIdx.x * blockDim.x + threadIdx.x;
    if (t < N_VOX * 8) {
        out[t] = bias4[t & 7];
    }
}

// ---------------------------------------------------------------------------
// Kernel 2: gather -> 32x32 per-offset GEMV -> vector-atomic scatter-add.
// One thread per (input,output) pair. Blocks of 256 pairs share one kernel
// offset k (PAIRS_PER_K % TPB == 0), so W[k] is staged in shared memory.
// Compute uses packed f32x2 FFMA (full-rate fp32 path on sm_103a).
// ---------------------------------------------------------------------------
__global__ void __launch_bounds__(TPB)
scatter_conv_kernel(const float4* __restrict__ in_feature,   // [N_VOX][8] f4
                    const float4* __restrict__ kernel_w,     // [K3][32][8] f4
                    const int2*   __restrict__ nbmap,        // [M] (src,dst)
                    float*        __restrict__ out)          // [N_VOX][32]
{
    __shared__ __align__(16) float Ws[C_IN * C_OUT];   // 4 KB: W[k][i][c]

    const int pair = blockIdx.x * TPB + threadIdx.x;
    const int k    = blockIdx.x / (PAIRS_PER_K / TPB);

    // Stage W[k] (1024 floats) with 256 float4 loads — one per thread.
    reinterpret_cast<float4*>(Ws)[threadIdx.x] =
        kernel_w[k * (C_IN * C_OUT / 4) + threadIdx.x];
    __syncthreads();

    const int2 ij = nbmap[pair];

    // Gather input row (32 floats = 8 x LDG.128)
    const float4* __restrict__ xrow = in_feature + (size_t)ij.x * 8;
    float4 xv[8];
#pragma unroll
    for (int q = 0; q < 8; q++) xv[q] = xrow[q];

    // 16 packed f32x2 accumulators = 32 output channels
    unsigned long long acc[16];
#pragma unroll
    for (int c = 0; c < 16; c++) acc[c] = 0ull;   // (0.0f, 0.0f)

#pragma unroll
    for (int q = 0; q < 8; q++) {
        float xs[4] = {xv[q].x, xv[q].y, xv[q].z, xv[q].w};
#pragma unroll
        for (int r = 0; r < 4; r++) {
            const int i = q * 4 + r;
            unsigned long long x2;
            {
                unsigned int xb = __float_as_uint(xs[r]);
                asm("mov.b64 %0, {%1, %1};" : "=l"(x2) : "r"(xb));
            }
            // W row i: 32 floats = 8 x LDS.128 (broadcast, conflict-free)
            const ulonglong2* __restrict__ wrow =
                reinterpret_cast<const ulonglong2*>(Ws + i * C_OUT);
#pragma unroll
            for (int c = 0; c < 8; c++) {
                ulonglong2 w = wrow[c];
                asm("fma.rn.f32x2 %0, %1, %2, %0;"
                    : "+l"(acc[2 * c])     : "l"(x2), "l"(w.x));
                asm("fma.rn.f32x2 %0, %1, %2, %0;"
                    : "+l"(acc[2 * c + 1]) : "l"(x2), "l"(w.y));
            }
        }
    }

    // Scatter-add: 8 x red.global.add.v4.f32 (16B vector atomics, no return)
    float* __restrict__ orow = out + (size_t)ij.y * C_OUT;
#pragma unroll
    for (int c = 0; c < 8; c++) {
        unsigned int a0, a1, a2, a3;
        asm("mov.b64 {%0,%1}, %2;" : "=r"(a0), "=r"(a1) : "l"(acc[2 * c]));
        asm("mov.b64 {%0,%1}, %2;" : "=r"(a2), "=r"(a3) : "l"(acc[2 * c + 1]));
        asm volatile("red.global.add.v4.f32 [%0], {%1,%2,%3,%4};"
                     :: "l"(orow + c * 4),
                        "f"(__uint_as_float(a0)), "f"(__uint_as_float(a1)),
                        "f"(__uint_as_float(a2)), "f"(__uint_as_float(a3))
                     : "memory");
    }
}

// ---------------------------------------------------------------------------
// Inputs (metadata order): in_feature f32[N_VOX,32], kernel f32[27,32,32],
// bias f32[32], nbmap i32[M,2], nbsizes i32[27]. Output f32[N_VOX,32].
// ---------------------------------------------------------------------------
extern "C" void kernel_launch(void* const* d_in, const int* in_sizes, int n_in,
                              void* d_out, int out_size) {
    const float4* in_feature = (const float4*)d_in[0];
    const float4* kernel_w   = (const float4*)d_in[1];
    const float4* bias4      = (const float4*)d_in[2];
    const int2*   nbmap      = (const int2*)d_in[3];
    float*        out        = (float*)d_out;

    init_bias_kernel<<<(N_VOX * 8 + 255) / 256, 256>>>((float4*)out, bias4);
    scatter_conv_kernel<<<M_TOTAL / TPB, TPB>>>(in_feature, kernel_w, nbmap, out);
}